// round 16
// baseline (speedup 1.0000x reference)
#include <cuda_runtime.h>
#include <cstdint>
#include <math.h>

#define Bn 8
#define Nn 1024
#define Dn 1024
#define Hn 4096
#define En 16
#define CAP 80
#define SPLITK 4

#define NT 256      // block tile N
#define KT 32       // block tile K
#define STAGES 4
#define CONS_T 320  // 10 consumer warps (5M x 2N, warp tile 16x128)
#define PROD_T 128  // 4 producer warps
#define THREADS (CONS_T + PROD_T)

// stage layout (u32 units): AH[80][20], AL[80][20], BH[32][128], BL[32][128]
#define APS 20
#define OFF_AH 0
#define OFF_AL 1600
#define OFF_BH 3200
#define OFF_BL 7296
#define STAGE_U32 11392
#define MB_OFF_U32 (STAGES * STAGE_U32)              // 45568
#define SMEM_BYTES (MB_OFF_U32 * 4 + 128)            // 182400

// zero-fill bookkeeping (out rows >= CAP, phase-1 consumer prologue)
#define ZF4_PER_B 241664
#define OF4_PER_B 262144
#define ZF4_SKIP  20480
#define ZF4_PER_CTA 15104

__device__ float g_hidden[(size_t)Bn * CAP * Hn];
__device__ float g_partial[(size_t)SPLITK * Bn * CAP * Dn];
__device__ int g_done[Bn][4];   // gemm1 k-chunk completion (4 CTAs each)
__device__ int g_fin[Bn];       // gemm2 spin-passed count (resets g_done)
__device__ int g_red[Bn][4];    // split completion per (b, ntile)

__device__ __forceinline__ float gelu_exact(float x) {
    return 0.5f * x * (1.0f + erff(x * 0.70710678118654752440f));
}
__device__ __forceinline__ uint32_t smem_u32(const void* p) {
    uint32_t a;
    asm("{ .reg .u64 t; cvta.to.shared.u64 t, %1; cvt.u32.u64 %0, t; }" : "=r"(a) : "l"(p));
    return a;
}
__device__ __forceinline__ void split2(float x, float y, uint32_t& hi, uint32_t& lo) {
    uint32_t bx = __float_as_uint(x), by = __float_as_uint(y);
    asm("prmt.b32 %0, %1, %2, 0x7632;" : "=r"(hi) : "r"(bx), "r"(by));
    float lx = x - __uint_as_float(bx & 0xFFFF0000u);
    float ly = y - __uint_as_float(by & 0xFFFF0000u);
    asm("cvt.rn.bf16x2.f32 %0, %1, %2;" : "=r"(lo) : "f"(ly), "f"(lx));
}
__device__ __forceinline__ void mma_bf16(
    float* acc, uint32_t a0, uint32_t a1, uint32_t a2, uint32_t a3,
    uint32_t b0, uint32_t b1)
{
    asm volatile(
        "mma.sync.aligned.m16n8k16.row.col.f32.bf16.bf16.f32 "
        "{%0,%1,%2,%3}, {%4,%5,%6,%7}, {%8,%9}, {%0,%1,%2,%3};"
        : "+f"(acc[0]), "+f"(acc[1]), "+f"(acc[2]), "+f"(acc[3])
        : "r"(a0), "r"(a1), "r"(a2), "r"(a3), "r"(b0), "r"(b1));
}
#define LDSM_X4(r0, r1, r2, r3, addr) \
    asm volatile("ldmatrix.sync.aligned.m8n8.x4.shared.b16 {%0,%1,%2,%3}, [%4];" \
        : "=r"(r0), "=r"(r1), "=r"(r2), "=r"(r3) : "r"(addr))
#define LDSM_X4T(r0, r1, r2, r3, addr) \
    asm volatile("ldmatrix.sync.aligned.m8n8.x4.trans.shared.b16 {%0,%1,%2,%3}, [%4];" \
        : "=r"(r0), "=r"(r1), "=r"(r2), "=r"(r3) : "r"(addr))

__device__ __forceinline__ void mbar_init(uint32_t a, uint32_t cnt) {
    asm volatile("mbarrier.init.shared.b64 [%0], %1;" :: "r"(a), "r"(cnt) : "memory");
}
__device__ __forceinline__ void mbar_arrive(uint32_t a) {
    asm volatile("mbarrier.arrive.shared.b64 _, [%0];" :: "r"(a) : "memory");
}
__device__ __forceinline__ void mbar_wait(uint32_t a, uint32_t parity) {
    uint32_t done;
    asm volatile(
        "{\n\t.reg .pred p;\n\t"
        "mbarrier.try_wait.parity.shared.b64 p, [%1], %2;\n\t"
        "selp.b32 %0, 1, 0, p;\n\t}"
        : "=r"(done) : "r"(a), "r"(parity) : "memory");
    while (!done) {
        asm volatile(
            "{\n\t.reg .pred p;\n\t"
            "mbarrier.try_wait.parity.shared.b64 p, [%1], %2, 0x989680;\n\t"
            "selp.b32 %0, 1, 0, p;\n\t}"
            : "=r"(done) : "r"(a), "r"(parity) : "memory");
    }
}

// ---------------------------------------------------------------------------
// Warp-specialized GEMM phase. tile_base gives the absolute tile index of
// j=0 so mbarrier parities continue correctly across phases sharing the ring.
// ---------------------------------------------------------------------------
template <bool GELU, bool ZFILL>
__device__ __forceinline__ void gemm_core(
    const float* __restrict__ A, int lda,
    const float* __restrict__ Bg, int ldb,
    int n0, int kbase, int ktiles,
    float* __restrict__ Out, int ldo,
    float* __restrict__ Zout, int cta_lin, int tile_base)
{
    extern __shared__ uint32_t Sm[];
    const uint32_t su = smem_u32(Sm);
    const int tid = threadIdx.x;
    const int wid = tid >> 5;
    const int lid = tid & 31;
    const uint32_t mb = su + MB_OFF_U32 * 4;

    if (wid < 10) {
        // ================= CONSUMER =================
        const int wm = wid >> 1;
        const int wn = wid & 1;
        const int g = lid >> 2;
        const int c = lid & 3;

        if (ZFILL) {
            const float4 z = make_float4(0.f, 0.f, 0.f, 0.f);
            const int zbase = cta_lin * ZF4_PER_CTA;
            #pragma unroll 4
            for (int r = 0; r < 48; r++) {
                int local = r * CONS_T + tid;
                if (local < ZF4_PER_CTA) {
                    int zi = zbase + local;
                    int b = zi / ZF4_PER_B;
                    int off = zi - b * ZF4_PER_B;
                    reinterpret_cast<float4*>(Zout)
                        [(size_t)b * OF4_PER_B + ZF4_SKIP + off] = z;
                }
            }
        }

        const int a_row = wm * 16 + (lid & 7) + ((lid >> 3) & 1) * 8;
        const uint32_t a_lds = (uint32_t)(a_row * APS + (lid >> 4) * 4) * 4;
        const int krow = lid & 15;
        uint32_t b_lds[8];
        #pragma unroll
        for (int t = 0; t < 8; t++) {
            int chunk = (wn * 16 + t * 2 + (lid >> 4)) ^ (krow & 7);
            b_lds[t] = (uint32_t)(krow * 512 + chunk * 16);
        }

        float acc[16][4];
        #pragma unroll
        for (int j = 0; j < 16; j++)
            #pragma unroll
            for (int i = 0; i < 4; i++) acc[j][i] = 0.0f;

        int s = 0;
        for (int j = 0; j < ktiles; j++) {
            const int n = tile_base + j;
            mbar_wait(mb + s * 8, (uint32_t)((n / STAGES) & 1));
            const uint32_t base = su + (uint32_t)s * (STAGE_U32 * 4);

            #pragma unroll
            for (int q = 0; q < 2; q++) {
                uint32_t ah0, ah1, ah2, ah3, al0, al1, al2, al3;
                LDSM_X4(ah0, ah1, ah2, ah3, base + OFF_AH * 4 + a_lds + q * 32);
                LDSM_X4(al0, al1, al2, al3, base + OFF_AL * 4 + a_lds + q * 32);
                #pragma unroll
                for (int t = 0; t < 8; t++) {
                    uint32_t bh0, bh1, bh2, bh3, bl0, bl1, bl2, bl3;
                    const uint32_t boff = b_lds[t] + q * 8192;
                    LDSM_X4T(bh0, bh1, bh2, bh3, base + OFF_BH * 4 + boff);
                    LDSM_X4T(bl0, bl1, bl2, bl3, base + OFF_BL * 4 + boff);
                    mma_bf16(acc[t * 2 + 0], ah0, ah1, ah2, ah3, bh0, bh1);
                    mma_bf16(acc[t * 2 + 0], ah0, ah1, ah2, ah3, bl0, bl1);
                    mma_bf16(acc[t * 2 + 0], al0, al1, al2, al3, bh0, bh1);
                    mma_bf16(acc[t * 2 + 1], ah0, ah1, ah2, ah3, bh2, bh3);
                    mma_bf16(acc[t * 2 + 1], ah0, ah1, ah2, ah3, bl2, bl3);
                    mma_bf16(acc[t * 2 + 1], al0, al1, al2, al3, bh2, bh3);
                }
            }
            mbar_arrive(mb + 64 + s * 8);
            if (++s == STAGES) s = 0;
        }

        #pragma unroll
        for (int jf = 0; jf < 16; jf++) {
            const int n = n0 + wn * 128 + jf * 8 + 2 * c;
            #pragma unroll
            for (int h = 0; h < 2; h++) {
                const int m = wm * 16 + g + 8 * h;
                float2 v;
                v.x = acc[jf][2 * h + 0];
                v.y = acc[jf][2 * h + 1];
                if (GELU) { v.x = gelu_exact(v.x); v.y = gelu_exact(v.y); }
                *reinterpret_cast<float2*>(&Out[(size_t)m * ldo + n]) = v;
            }
        }
    } else {
        // ================= PRODUCER =================
        const int ptid = tid - CONS_T;
        int s = 0;
        for (int j = 0; j < ktiles; j++) {
            const int n = tile_base + j;
            if (n >= STAGES)
                mbar_wait(mb + 64 + s * 8, (uint32_t)((n / STAGES + 1) & 1));
            const int k0 = kbase + j * KT;
            uint32_t* base = Sm + (size_t)s * STAGE_U32;

            float4 av[5];
            #pragma unroll
            for (int r = 0; r < 5; r++) {
                int idx = ptid + r * 128;
                av[r] = *reinterpret_cast<const float4*>(
                    &A[(size_t)(idx >> 3) * lda + k0 + (idx & 7) * 4]);
            }
            #pragma unroll
            for (int r = 0; r < 5; r++) {
                int idx = ptid + r * 128;
                uint32_t h0, l0, h1, l1;
                split2(av[r].x, av[r].y, h0, l0);
                split2(av[r].z, av[r].w, h1, l1);
                int d = (idx >> 3) * APS + (idx & 7) * 2;
                *reinterpret_cast<uint2*>(base + OFF_AH + d) = make_uint2(h0, h1);
                *reinterpret_cast<uint2*>(base + OFF_AL + d) = make_uint2(l0, l1);
            }
            #pragma unroll
            for (int half = 0; half < 2; half++) {
                float4 bv[8];
                #pragma unroll
                for (int r = 0; r < 8; r++) {
                    int idx = ptid + (half * 8 + r) * 128;
                    bv[r] = *reinterpret_cast<const float4*>(
                        &Bg[(size_t)(k0 + (idx >> 6)) * ldb + n0 + (idx & 63) * 4]);
                }
                #pragma unroll
                for (int r = 0; r < 8; r++) {
                    int idx = ptid + (half * 8 + r) * 128;
                    int k = idx >> 6, n4 = idx & 63;
                    int d = k * 128 + (((n4 >> 1) ^ (k & 7)) << 2) + (n4 & 1) * 2;
                    uint32_t h0, l0, h1, l1;
                    split2(bv[r].x, bv[r].y, h0, l0);
                    split2(bv[r].z, bv[r].w, h1, l1);
                    *reinterpret_cast<uint2*>(base + OFF_BH + d) = make_uint2(h0, h1);
                    *reinterpret_cast<uint2*>(base + OFF_BL + d) = make_uint2(l0, l1);
                }
            }
            mbar_arrive(mb + s * 8);
            if (++s == STAGES) s = 0;
        }
    }
}

// ---------------------------------------------------------------------------
// Fused MoE: gemm1 -> device handshake -> gemm2 -> fused split-K reduce.
// 128 CTAs (one wave, all resident -> spin-safe).
// ---------------------------------------------------------------------------
__global__ __launch_bounds__(THREADS, 1)
void moe_kernel(const float* __restrict__ inputs, const int* __restrict__ y,
                const float* __restrict__ w1, const float* __restrict__ w2,
                float* __restrict__ out)
{
    extern __shared__ uint32_t Sm[];
    const uint32_t su = smem_u32(Sm);
    const int tid = threadIdx.x;
    const int cid = blockIdx.x;
    const uint32_t mb = su + MB_OFF_U32 * 4;
    __shared__ int s_win;

    if (tid == 0) {
        #pragma unroll
        for (int s = 0; s < STAGES; s++) {
            mbar_init(mb + s * 8, PROD_T);
            mbar_init(mb + 64 + s * 8, CONS_T);
        }
    }
    __syncthreads();

    // ---------------- phase 1: gemm1 ----------------
    const int b1 = cid >> 4;
    const int nt1 = cid & 15;
    const int e1 = y[b1] % En;
    gemm_core<true, true>(inputs + (size_t)b1 * Nn * Dn, Dn,
                          w1 + (size_t)e1 * Dn * Hn, Hn,
                          nt1 * NT, 0, Dn / KT,
                          g_hidden + (size_t)b1 * CAP * Hn, Hn,
                          out, cid, /*tile_base=*/0);
    if (tid < CONS_T) {
        asm volatile("bar.sync 1, %0;" :: "n"(CONS_T) : "memory");
        if (tid == 0) {
            __threadfence();
            atomicAdd(&g_done[b1][nt1 >> 2], 1);
        }
    }

    // ---------------- handshake ----------------
    const int b2 = cid >> 4;
    const int nt2 = cid & 3;
    const int split = (cid >> 2) & 3;
    if (tid == 0) {
        while (atomicAdd(&g_done[b2][split], 0) < 4) __nanosleep(64);
        int old = atomicAdd(&g_fin[b2], 1);
        if (old == 15) {    // all 16 CTAs of batch b2 passed their spins
            g_done[b2][0] = 0; g_done[b2][1] = 0;
            g_done[b2][2] = 0; g_done[b2][3] = 0;
            g_fin[b2] = 0;
        }
    }
    __syncthreads();
    __threadfence();

    // ---------------- phase 2: gemm2 ----------------
    const int e2 = y[b2] % En;
    gemm_core<false, false>(g_hidden + (size_t)b2 * CAP * Hn, Hn,
                            w2 + (size_t)e2 * Hn * Dn, Dn,
                            nt2 * NT, split * (Hn / SPLITK), (Hn / SPLITK) / KT,
                            g_partial + ((size_t)split * Bn + b2) * CAP * Dn, Dn,
                            nullptr, 0, /*tile_base=*/Dn / KT);

    // ---------------- phase 3: fused split-K reduce ----------------
    if (tid < CONS_T) {
        asm volatile("bar.sync 1, %0;" :: "n"(CONS_T) : "memory");
        if (tid == 0) {
            __threadfence();
            int old = atomicAdd(&g_red[b2][nt2], 1);
            s_win = (old == 3);
        }
        asm volatile("bar.sync 1, %0;" :: "n"(CONS_T) : "memory");
        if (s_win) {
            __threadfence();   // acquire other splits' partials
            const int ncol0 = nt2 * NT;
            for (int i = tid; i < CAP * NT / 4; i += CONS_T) {
                int tok = i / (NT / 4);
                int d4 = i % (NT / 4);
                size_t po = ((size_t)b2 * CAP + tok) * Dn + ncol0 + d4 * 4;
                float4 v = *reinterpret_cast<const float4*>(&g_partial[po]);
                #pragma unroll
                for (int s = 1; s < SPLITK; s++) {
                    const float4 p = *reinterpret_cast<const float4*>(
                        &g_partial[(size_t)s * Bn * CAP * Dn + po]);
                    v.x += p.x; v.y += p.y; v.z += p.z; v.w += p.w;
                }
                *reinterpret_cast<float4*>(
                    &out[((size_t)b2 * Nn + tok) * Dn + ncol0 + d4 * 4]) = v;
            }
            if (tid == 0) g_red[b2][nt2] = 0;
        }
    }
}

extern "C" void kernel_launch(void* const* d_in, const int* in_sizes, int n_in,
                              void* d_out, int out_size) {
    const float* inputs = (const float*)d_in[0];   // (8, 1024, 1024) f32
    const int*   y      = (const int*)d_in[1];     // (8,) i32
    const float* w1     = (const float*)d_in[2];   // (16, 1024, 4096) f32
    const float* w2     = (const float*)d_in[3];   // (16, 4096, 1024) f32
    float* out = (float*)d_out;                    // (8, 1024, 1024) f32

    cudaFuncSetAttribute(moe_kernel, cudaFuncAttributeMaxDynamicSharedMemorySize, SMEM_BYTES);
    moe_kernel<<<128, THREADS, SMEM_BYTES>>>(inputs, y, w1, w2, out);
}